// round 10
// baseline (speedup 1.0000x reference)
#include <cuda_runtime.h>
#include <cstdint>

#define D 128
#define MAXN 100000
#define BM 64
#define NT 512
#define BN_EPS 1e-5f
// compensation for tf32 RZ truncation of A operands (E[rel loss] ~ 3.5e-4)
#define TRUNC_COMP 1.00035f

// ---------------- scratch (device globals; no runtime allocation) -----------
__device__ __align__(16) float g_agg[(size_t)MAXN * D];
__device__ __align__(16) float g_y[(size_t)MAXN * D];
__device__ float g_csrc[MAXN];
__device__ float g_cdst[MAXN];
__device__ int   g_odeg[MAXN];
__device__ int   g_ideg[MAXN];
__device__ __align__(16) float g_colsum[D];
__device__ __align__(16) float g_colsq[D];
__device__ __align__(16) float g_scale[D];
__device__ __align__(16) float g_shift[D];

// ---------------- degree histograms -----------------------------------------
__global__ void k_degrees(const int* __restrict__ src, const int* __restrict__ dst, int E) {
    int e = blockIdx.x * blockDim.x + threadIdx.x;
    if (e < E) {
        atomicAdd(&g_odeg[src[e]], 1);
        atomicAdd(&g_ideg[dst[e]], 1);
    }
}

__global__ void k_cnorm(int N) {
    int i = blockIdx.x * blockDim.x + threadIdx.x;
    if (i < N) {
        g_csrc[i] = rsqrtf(fmaxf((float)g_odeg[i], 1.0f));
        g_cdst[i] = rsqrtf(fmaxf((float)g_ideg[i], 1.0f));
    }
}

// ---------------- edge aggregation: 4 edges per warp (8 lanes/edge) ----------
__global__ __launch_bounds__(256) void k_aggregate(
    const float4* __restrict__ x4, const int* __restrict__ src,
    const int* __restrict__ dst, int E) {
    int t = blockIdx.x * blockDim.x + threadIdx.x;
    int e = (t >> 5) * 4 + ((t & 31) >> 3);
    if (e >= E) return;
    int c = t & 7;
    int s = __ldg(&src[e]);
    int d = __ldg(&dst[e]);
    float cs = __ldg(&g_csrc[s]);
    const float4* xb = x4 + (size_t)s * 32;
    float4 v0 = __ldg(xb + c), v1 = __ldg(xb + c + 8);
    float4 v2 = __ldg(xb + c + 16), v3 = __ldg(xb + c + 24);
    float* p = g_agg + (size_t)d * D;
#define RED4(vv, off)                                                          \
    asm volatile("red.global.add.v4.f32 [%0], {%1, %2, %3, %4};"               \
                 :: "l"(p + (off) * 4), "f"((vv).x * cs), "f"((vv).y * cs),    \
                    "f"((vv).z * cs), "f"((vv).w * cs) : "memory")
    RED4(v0, c); RED4(v1, c + 8); RED4(v2, c + 16); RED4(v3, c + 24);
#undef RED4
}

// ---------------- tf32 tensor-core fused dual GEMM ---------------------------
__device__ __forceinline__ unsigned f2tf(float f) {
    unsigned u; asm("cvt.rna.tf32.f32 %0, %1;" : "=r"(u) : "f"(f)); return u;
}

#define MMA_TF32(d, a, b0_, b1_) \
    asm volatile("mma.sync.aligned.m16n8k8.row.col.f32.tf32.tf32.f32 " \
        "{%0,%1,%2,%3},{%4,%5,%6,%7},{%8,%9},{%0,%1,%2,%3};" \
        : "+f"(d[0]), "+f"(d[1]), "+f"(d[2]), "+f"(d[3]) \
        : "r"(a[0]), "r"(a[1]), "r"(a[2]), "r"(a[3]), "r"(b0_), "r"(b1_))

// one (tile,branch) stage: raw fp32 rows -> swizzled smem via cp.async (512 thr)
__device__ __forceinline__ void stage_load(unsigned* buf, const float4* __restrict__ srcb,
                                           int row0, int N, int tid) {
#pragma unroll
    for (int i = 0; i < 4; i++) {
        int idx = tid + i * NT;
        int row = idx >> 5, kq = idx & 31;
        int grow = row0 + row;
        unsigned daddr = (unsigned)__cvta_generic_to_shared(
            buf + row * 128 + ((kq * 4) ^ ((row & 7) * 4)));
        const float4* s = srcb + (size_t)(grow < N ? grow : 0) * 32 + kq;
        int sz = grow < N ? 16 : 0;
        asm volatile("cp.async.cg.shared.global [%0], [%1], 16, %2;"
                     :: "r"(daddr), "l"(s), "r"(sz));
    }
}

// jp-loop for one branch; A operands are RAW fp32 bits (MMA truncates to tf32;
// bias compensated via TRUNC_COMP folded into the weights). Warp tile m16 x n32.
#define MMA_STAGE(ACC, BR)                                                         \
    _Pragma("unroll")                                                              \
    for (int jp = 0; jp < 8; jp++) {                                               \
        unsigned a[2][4];                                                          \
        {                                                                          \
            const unsigned* base = asb + (mw * 16 + gid) * 128;                    \
            _Pragma("unroll")                                                      \
            for (int dj = 0; dj < 2; dj++) {                                       \
                int k0 = jp * 16 + dj * 8 + tig;                                   \
                a[dj][0] = base[(k0) ^ swz];                                       \
                a[dj][1] = base[1024 + ((k0) ^ swz)];                              \
                a[dj][2] = base[(k0 + 4) ^ swz];                                   \
                a[dj][3] = base[1024 + ((k0 + 4) ^ swz)];                          \
            }                                                                      \
        }                                                                          \
        _Pragma("unroll")                                                          \
        for (int t = 0; t < 4; t++) {                                              \
            int region = (nw * 2 + (BR)) * 4 + t;                                  \
            uint4 bf = *(const uint4*)(ws + region * 1024 + lane * 32 +            \
                                       ((jp ^ (lane & 7)) << 2));                  \
            MMA_TF32(ACC[t], a[0], bf.x, bf.y);                                    \
            MMA_TF32(ACC[t], a[1], bf.z, bf.w);                                    \
        }                                                                          \
    }

// Block: 512 thr = 16 warps = 4(m) x 4(n); warp tile m16 x n32, both branches.
// smem: ws = fragment-major tf32 W/Wr (128KB), as0/as1 = 32KB A stages.
__global__ __launch_bounds__(NT, 1) void k_gemm_tf32(
    const float4* __restrict__ x4, const float* __restrict__ W,
    const float* __restrict__ bb, const float* __restrict__ Wr,
    const float* __restrict__ brr, int N, int numTiles)
{
    extern __shared__ unsigned smem_u[];
    unsigned* ws  = smem_u;           // 32768 words = 128KB
    unsigned* as0 = smem_u + 32768;   //  8192 words =  32KB
    unsigned* as1 = smem_u + 40960;   //  8192 words =  32KB

    const int tid  = threadIdx.x;
    const int lane = tid & 31;
    const int wid  = tid >> 5;
    const int mw   = wid >> 2;     // 0..3 (m group of 16 rows)
    const int nw   = wid & 3;      // 0..3 (n group of 32 cols)
    const int tig  = lane & 3;
    const int gid  = lane >> 2;
    const int swz  = gid * 4;

    const float4* agg4 = (const float4*)g_agg;

    // ---- one-time: fragment-major packed W/Wr in tf32 (RNA, bias-compensated)
    for (int cell = tid; cell < 8192; cell += NT) {
        int j2  = cell & 7;
        int l   = (cell >> 3) & 31;
        int t   = (cell >> 8) & 3;
        int cbr = (cell >> 10) & 1;
        int cnw = (cell >> 11) & 3;
        const float* Wb = cbr ? Wr : W;
        int n  = cnw * 32 + t * 8 + (l >> 2);
        int k0 = j2 * 16 + (l & 3);
        uint4 v;
        v.x = f2tf(__ldg(&Wb[(k0     ) * D + n]) * TRUNC_COMP);
        v.y = f2tf(__ldg(&Wb[(k0 +  4) * D + n]) * TRUNC_COMP);
        v.z = f2tf(__ldg(&Wb[(k0 +  8) * D + n]) * TRUNC_COMP);
        v.w = f2tf(__ldg(&Wb[(k0 + 12) * D + n]) * TRUNC_COMP);
        int region = (cnw * 2 + cbr) * 4 + t;
        *(uint4*)(ws + region * 1024 + l * 32 + ((j2 ^ (l & 7)) << 2)) = v;
    }

    // biases for this thread's 8 output columns
    float b_[8], q_[8];
#pragma unroll
    for (int t = 0; t < 4; t++) {
        int col = nw * 32 + t * 8 + 2 * tig;
        b_[2 * t] = __ldg(&bb[col]);   b_[2 * t + 1] = __ldg(&bb[col + 1]);
        q_[2 * t] = __ldg(&brr[col]);  q_[2 * t + 1] = __ldg(&brr[col + 1]);
    }

    float ts[8], tq[8];
#pragma unroll
    for (int i = 0; i < 8; i++) { ts[i] = 0.f; tq[i] = 0.f; }

    const int nT = (numTiles - blockIdx.x + gridDim.x - 1) / gridDim.x;
    const int totalS = nT * 2;

    // prologue: stages 0 (agg of tile0) and 1 (x of tile0)
    stage_load(as0, agg4, blockIdx.x * BM, N, tid);
    asm volatile("cp.async.commit_group;");
    stage_load(as1, x4, blockIdx.x * BM, N, tid);
    asm volatile("cp.async.commit_group;");

    float acc0[4][4], acc1[4][4];

    for (int s = 0; s < totalS; s++) {
        const int br   = s & 1;
        const int tile = blockIdx.x + (s >> 1) * gridDim.x;
        const int row0 = tile * BM;

        asm volatile("cp.async.wait_group 1;");
        __syncthreads();
        const unsigned* asb = br ? as1 : as0;

        if (br == 0) {
#pragma unroll
            for (int t = 0; t < 4; t++)
#pragma unroll
                for (int r = 0; r < 4; r++) { acc0[t][r] = 0.f; acc1[t][r] = 0.f; }
            MMA_STAGE(acc0, 0)
        } else {
            MMA_STAGE(acc1, 1)
        }

        __syncthreads();  // all reads of asb done before overwrite

        int s2 = s + 2;
        if (s2 < totalS) {
            int t2 = blockIdx.x + (s2 >> 1) * gridDim.x;
            stage_load((s2 & 1) ? as1 : as0, (s2 & 1) ? x4 : agg4, t2 * BM, N, tid);
        }
        asm volatile("cp.async.commit_group;");

        if (br == 1) {
            // epilogue: h*c_dst + b -> relu, + relu(res+br), write y, BN sums
            int rA = row0 + mw * 16 + gid;
            int rB = rA + 8;
            float cdA = (rA < N) ? __ldg(&g_cdst[rA]) : 0.f;
            float cdB = (rB < N) ? __ldg(&g_cdst[rB]) : 0.f;
#pragma unroll
            for (int t = 0; t < 4; t++) {
                int col = nw * 32 + t * 8 + 2 * tig;
                if (rA < N) {
                    float v0 = fmaxf(acc0[t][0] * cdA + b_[2 * t], 0.f)
                             + fmaxf(acc1[t][0] + q_[2 * t], 0.f);
                    float v1 = fmaxf(acc0[t][1] * cdA + b_[2 * t + 1], 0.f)
                             + fmaxf(acc1[t][1] + q_[2 * t + 1], 0.f);
                    *(float2*)&g_y[(size_t)rA * D + col] = make_float2(v0, v1);
                    ts[2 * t] += v0; tq[2 * t] += v0 * v0;
                    ts[2 * t + 1] += v1; tq[2 * t + 1] += v1 * v1;
                }
                if (rB < N) {
                    float v2 = fmaxf(acc0[t][2] * cdB + b_[2 * t], 0.f)
                             + fmaxf(acc1[t][2] + q_[2 * t], 0.f);
                    float v3 = fmaxf(acc0[t][3] * cdB + b_[2 * t + 1], 0.f)
                             + fmaxf(acc1[t][3] + q_[2 * t + 1], 0.f);
                    *(float2*)&g_y[(size_t)rB * D + col] = make_float2(v2, v3);
                    ts[2 * t] += v2; tq[2 * t] += v2 * v2;
                    ts[2 * t + 1] += v3; tq[2 * t + 1] += v3 * v3;
                }
            }
        }
    }

    // ---- BN sums: lanes gid 0..7 hold identical column sets -> reduce ----
#pragma unroll
    for (int i = 0; i < 8; i++) {
#pragma unroll
        for (int m = 4; m <= 16; m <<= 1) {
            ts[i] += __shfl_xor_sync(0xffffffffu, ts[i], m);
            tq[i] += __shfl_xor_sync(0xffffffffu, tq[i], m);
        }
    }
    if (gid == 0) {
#pragma unroll
        for (int i = 0; i < 8; i++) {
            int col = nw * 32 + (i >> 1) * 8 + 2 * tig + (i & 1);
            atomicAdd(&g_colsum[col], ts[i]);
            atomicAdd(&g_colsq[col], tq[i]);
        }
    }
}

// ---------------- BN parameter fold + apply ----------------------------------
__global__ void k_bnparams(const float* __restrict__ gamma, const float* __restrict__ beta, float invN) {
    int j = threadIdx.x;
    float mean = g_colsum[j] * invN;
    float var = fmaxf(g_colsq[j] * invN - mean * mean, 0.f);
    float s = rsqrtf(var + BN_EPS) * __ldg(&gamma[j]);
    g_scale[j] = s;
    g_shift[j] = __ldg(&beta[j]) - mean * s;
}

__global__ __launch_bounds__(256) void k_bnapply(float4* __restrict__ out4, int total4) {
    int i = blockIdx.x * blockDim.x + threadIdx.x;
    if (i >= total4) return;
    const float4* y4 = (const float4*)g_y;
    const float4* s4 = (const float4*)g_scale;
    const float4* t4 = (const float4*)g_shift;
    int c = i & 31;
    float4 v = y4[i];
    float4 s = s4[c];
    float4 t = t4[c];
    out4[i] = make_float4(v.x * s.x + t.x, v.y * s.y + t.y,
                          v.z * s.z + t.z, v.w * s.w + t.w);
}

// ---------------- launch ------------------------------------------------------
extern "C" void kernel_launch(void* const* d_in, const int* in_sizes, int n_in,
                              void* d_out, int out_size) {
    const float* x     = (const float*)d_in[0];
    const float* W     = (const float*)d_in[1];
    const float* b     = (const float*)d_in[2];
    const float* Wr    = (const float*)d_in[3];
    const float* br    = (const float*)d_in[4];
    const float* gamma = (const float*)d_in[5];
    const float* beta  = (const float*)d_in[6];
    const int*   src   = (const int*)d_in[7];
    const int*   dst   = (const int*)d_in[8];

    const int N = in_sizes[0] / D;
    const int E = in_sizes[7];

    void *p_agg, *p_odeg, *p_ideg, *p_colsum, *p_colsq;
    cudaGetSymbolAddress(&p_agg, g_agg);
    cudaGetSymbolAddress(&p_odeg, g_odeg);
    cudaGetSymbolAddress(&p_ideg, g_ideg);
    cudaGetSymbolAddress(&p_colsum, g_colsum);
    cudaGetSymbolAddress(&p_colsq, g_colsq);

    cudaMemsetAsync(p_agg, 0, (size_t)N * D * sizeof(float));
    cudaMemsetAsync(p_odeg, 0, (size_t)N * sizeof(int));
    cudaMemsetAsync(p_ideg, 0, (size_t)N * sizeof(int));
    cudaMemsetAsync(p_colsum, 0, D * sizeof(float));
    cudaMemsetAsync(p_colsq, 0, D * sizeof(float));

    k_degrees<<<(E + 255) / 256, 256>>>(src, dst, E);
    k_cnorm<<<(N + 255) / 256, 256>>>(N);

    {
        // 4 edges per warp -> 32 edges per 256-thread block
        int blocks = (E + 31) / 32;
        k_aggregate<<<blocks, 256>>>((const float4*)x, src, dst, E);
    }

    {
        const int smemBytes = 49152 * (int)sizeof(unsigned);  // 192 KB
        cudaFuncSetAttribute(k_gemm_tf32, cudaFuncAttributeMaxDynamicSharedMemorySize, smemBytes);
        int numTiles = (N + BM - 1) / BM;
        int grid = numTiles < 152 ? numTiles : 152;
        k_gemm_tf32<<<grid, NT, smemBytes>>>(
            (const float4*)x, W, b, Wr, br, N, numTiles);
    }

    k_bnparams<<<1, D>>>(gamma, beta, 1.0f / (float)N);
    {
        int total4 = N * (D / 4);
        k_bnapply<<<(total4 + 255) / 256, 256>>>((float4*)d_out, total4);
    }
}

// round 12
// speedup vs baseline: 1.0101x; 1.0101x over previous
#include <cuda_runtime.h>
#include <cuda_fp16.h>
#include <cstdint>

#define D 128
#define MAXN 100000
#define BM 128
#define BN_EPS 1e-5f
// compensation for tf32 RZ truncation of A operands (E[rel loss] ~ 3.5e-4)
#define TRUNC_COMP 1.00035f

// ---------------- scratch (device globals; no runtime allocation) -----------
__device__ __align__(16) float g_agg[(size_t)MAXN * D];
__device__ __align__(16) float g_y[(size_t)MAXN * D];
__device__ float g_csrc[MAXN];
__device__ float g_cdst[MAXN];
__device__ int   g_odeg[MAXN];
__device__ int   g_ideg[MAXN];
__device__ __align__(16) float g_colsum[D];
__device__ __align__(16) float g_colsq[D];
__device__ __align__(16) float g_scale[D];
__device__ __align__(16) float g_shift[D];

// ---------------- degree histograms -----------------------------------------
__global__ void k_degrees(const int* __restrict__ src, const int* __restrict__ dst, int E) {
    int e = blockIdx.x * blockDim.x + threadIdx.x;
    if (e < E) {
        atomicAdd(&g_odeg[src[e]], 1);
        atomicAdd(&g_ideg[dst[e]], 1);
    }
}

// also zeroes the BN accumulators (saves two memset launches)
__global__ void k_cnorm(int N) {
    int i = blockIdx.x * blockDim.x + threadIdx.x;
    if (i < D) { g_colsum[i] = 0.f; g_colsq[i] = 0.f; }
    if (i < N) {
        g_csrc[i] = rsqrtf(fmaxf((float)g_odeg[i], 1.0f));
        g_cdst[i] = rsqrtf(fmaxf((float)g_ideg[i], 1.0f));
    }
}

// ---------------- edge aggregation: 8 edges per warp (4 lanes/edge) ----------
__global__ __launch_bounds__(256) void k_aggregate(
    const float4* __restrict__ x4, const int* __restrict__ src,
    const int* __restrict__ dst, int E) {
    int t = blockIdx.x * blockDim.x + threadIdx.x;
    int e = (t >> 5) * 8 + ((t & 31) >> 2);
    if (e >= E) return;
    int c = t & 3;
    int s = __ldg(&src[e]);
    int d = __ldg(&dst[e]);
    float cs = __ldg(&g_csrc[s]);
    const float4* xb = x4 + (size_t)s * 32;
    float4 v0 = __ldg(xb + c),      v1 = __ldg(xb + c + 4);
    float4 v2 = __ldg(xb + c + 8),  v3 = __ldg(xb + c + 12);
    float4 v4 = __ldg(xb + c + 16), v5 = __ldg(xb + c + 20);
    float4 v6 = __ldg(xb + c + 24), v7 = __ldg(xb + c + 28);
    float* p = g_agg + (size_t)d * D;
#define RED4(vv, off)                                                          \
    asm volatile("red.global.add.v4.f32 [%0], {%1, %2, %3, %4};"               \
                 :: "l"(p + (off) * 4), "f"((vv).x * cs), "f"((vv).y * cs),    \
                    "f"((vv).z * cs), "f"((vv).w * cs) : "memory")
    RED4(v0, c);      RED4(v1, c + 4);  RED4(v2, c + 8);  RED4(v3, c + 12);
    RED4(v4, c + 16); RED4(v5, c + 20); RED4(v6, c + 24); RED4(v7, c + 28);
#undef RED4
}

// ---------------- tf32 tensor-core fused dual GEMM ---------------------------
__device__ __forceinline__ unsigned f2tf(float f) {
    unsigned u; asm("cvt.rna.tf32.f32 %0, %1;" : "=r"(u) : "f"(f)); return u;
}

#define MMA_TF32(d, a, b0_, b1_) \
    asm volatile("mma.sync.aligned.m16n8k8.row.col.f32.tf32.tf32.f32 " \
        "{%0,%1,%2,%3},{%4,%5,%6,%7},{%8,%9},{%0,%1,%2,%3};" \
        : "+f"(d[0]), "+f"(d[1]), "+f"(d[2]), "+f"(d[3]) \
        : "r"(a[0]), "r"(a[1]), "r"(a[2]), "r"(a[3]), "r"(b0_), "r"(b1_))

// one 128-row tile stage: raw fp32 rows -> swizzled smem via cp.async (256 thr)
__device__ __forceinline__ void stage_load(unsigned* buf, const float4* __restrict__ srcb,
                                           int row0, int N, int tid) {
#pragma unroll
    for (int i = 0; i < 16; i++) {
        int idx = tid + i * 256;
        int row = idx >> 5, kq = idx & 31;
        int grow = row0 + row;
        unsigned daddr = (unsigned)__cvta_generic_to_shared(
            buf + row * 128 + ((kq * 4) ^ ((row & 7) * 4)));
        const float4* s = srcb + (size_t)(grow < N ? grow : 0) * 32 + kq;
        int sz = grow < N ? 16 : 0;
        asm volatile("cp.async.cg.shared.global [%0], [%1], 16, %2;"
                     :: "r"(daddr), "l"(s), "r"(sz));
    }
}

// MMA over one branch for the current 128-row stage. Warp tile m64 x n32.
#define MMA_STAGE(BR)                                                              \
    _Pragma("unroll")                                                              \
    for (int jp = 0; jp < 8; jp++) {                                               \
        unsigned a[4][2][4];                                                       \
        _Pragma("unroll")                                                          \
        for (int mf = 0; mf < 4; mf++) {                                           \
            const unsigned* base = asb + (mw * 64 + mf * 16 + gid) * 128;          \
            _Pragma("unroll")                                                      \
            for (int dj = 0; dj < 2; dj++) {                                       \
                int k0 = jp * 16 + dj * 8 + tig;                                   \
                a[mf][dj][0] = base[(k0) ^ swz];                                   \
                a[mf][dj][1] = base[1024 + ((k0) ^ swz)];                          \
                a[mf][dj][2] = base[(k0 + 4) ^ swz];                               \
                a[mf][dj][3] = base[1024 + ((k0 + 4) ^ swz)];                      \
            }                                                                      \
        }                                                                          \
        _Pragma("unroll")                                                          \
        for (int t = 0; t < 4; t++) {                                              \
            int region = (nw * 2 + (BR)) * 4 + t;                                  \
            uint4 bf = *(const uint4*)(ws + region * 1024 + lane * 32 +            \
                                       ((jp ^ (lane & 7)) << 2));                  \
            _Pragma("unroll")                                                      \
            for (int mf = 0; mf < 4; mf++) {                                       \
                MMA_TF32(acc[mf][t], a[mf][0], bf.x, bf.y);                        \
                MMA_TF32(acc[mf][t], a[mf][1], bf.z, bf.w);                        \
            }                                                                      \
        }                                                                          \
    }

// Block: 256 thr = 8 warps = 2(m) x 4(n); warp tile m64 x n32; BM=128 tiles.
// Branches sequential per tile, acc reused; branch-1 (res) result stashed fp16.
// smem: ws 128KB + stage 64KB + stash 32KB (128 rows x 64 half2) = 224KB.
__global__ __launch_bounds__(256, 1) void k_gemm_tf32(
    const float4* __restrict__ x4, const float* __restrict__ W,
    const float* __restrict__ bb, const float* __restrict__ Wr,
    const float* __restrict__ brr, int N, int numTiles)
{
    extern __shared__ unsigned smem_u[];
    unsigned* ws    = smem_u;           // 32768 words = 128KB
    unsigned* asb   = smem_u + 32768;   // 16384 words =  64KB (128-row stage)
    unsigned* stash = smem_u + 49152;   //  8192 words =  32KB (128 x 64 half2)

    const int tid  = threadIdx.x;
    const int lane = tid & 31;
    const int wid  = tid >> 5;
    const int mw   = wid >> 2;     // 0..1 (m group of 64 rows)
    const int nw   = wid & 3;      // 0..3 (n group of 32 cols)
    const int tig  = lane & 3;
    const int gid  = lane >> 2;
    const int swz  = gid * 4;

    const float4* agg4 = (const float4*)g_agg;

    // ---- one-time: fragment-major packed W/Wr in tf32 (RNA, bias-compensated)
    for (int cell = tid; cell < 8192; cell += 256) {
        int j2  = cell & 7;
        int l   = (cell >> 3) & 31;
        int t   = (cell >> 8) & 3;
        int cbr = (cell >> 10) & 1;
        int cnw = (cell >> 11) & 3;
        const float* Wb = cbr ? Wr : W;
        int n  = cnw * 32 + t * 8 + (l >> 2);
        int k0 = j2 * 16 + (l & 3);
        uint4 v;
        v.x = f2tf(__ldg(&Wb[(k0     ) * D + n]) * TRUNC_COMP);
        v.y = f2tf(__ldg(&Wb[(k0 +  4) * D + n]) * TRUNC_COMP);
        v.z = f2tf(__ldg(&Wb[(k0 +  8) * D + n]) * TRUNC_COMP);
        v.w = f2tf(__ldg(&Wb[(k0 + 12) * D + n]) * TRUNC_COMP);
        int region = (cnw * 2 + cbr) * 4 + t;
        *(uint4*)(ws + region * 1024 + l * 32 + ((j2 ^ (l & 7)) << 2)) = v;
    }

    // biases for this thread's 8 output columns
    float b_[8], q_[8];
#pragma unroll
    for (int t = 0; t < 4; t++) {
        int col = nw * 32 + t * 8 + 2 * tig;
        b_[2 * t] = __ldg(&bb[col]);   b_[2 * t + 1] = __ldg(&bb[col + 1]);
        q_[2 * t] = __ldg(&brr[col]);  q_[2 * t + 1] = __ldg(&brr[col + 1]);
    }

    float ts[8], tq[8];
#pragma unroll
    for (int i = 0; i < 8; i++) { ts[i] = 0.f; tq[i] = 0.f; }

    const int nT = (numTiles > blockIdx.x)
                 ? (numTiles - blockIdx.x + gridDim.x - 1) / gridDim.x : 0;

    // per-thread stash slots: row stride 64 half2-words (128 cols / 2).
    // col2 = nw*16 + t*4 + tig in [0,63]; word = row*64 + (col2 ^ ((row&7)*4))
    const int col2b = nw * 16 + tig;

    // prologue: stage x of tile 0
    stage_load(asb, x4, blockIdx.x * BM, N, tid);
    asm volatile("cp.async.commit_group;");

    for (int s = 0; s < nT; s++) {
        const int tile = blockIdx.x + s * gridDim.x;
        const int row0 = tile * BM;

        float acc[4][4][4];

        // ================= branch 1: res = x @ Wr =================
        asm volatile("cp.async.wait_group 0;");
        __syncthreads();                       // x stage visible
#pragma unroll
        for (int mf = 0; mf < 4; mf++)
#pragma unroll
            for (int t = 0; t < 4; t++)
#pragma unroll
                for (int r = 0; r < 4; r++) acc[mf][t][r] = 0.f;
        MMA_STAGE(1)
        __syncthreads();                       // all x reads done
        stage_load(asb, agg4, row0, N, tid);   // agg load overlaps epi below
        asm volatile("cp.async.commit_group;");

        // epi: stash relu(res + q) as fp16 (thread-private slots, no sync)
#pragma unroll
        for (int mf = 0; mf < 4; mf++) {
            int lrA = mw * 64 + mf * 16 + gid;
            int lrB = lrA + 8;
#pragma unroll
            for (int t = 0; t < 4; t++) {
                int c2 = col2b + t * 4;
                __half2 hA = __floats2half2_rn(
                    fmaxf(acc[mf][t][0] + q_[2 * t], 0.f),
                    fmaxf(acc[mf][t][1] + q_[2 * t + 1], 0.f));
                __half2 hB = __floats2half2_rn(
                    fmaxf(acc[mf][t][2] + q_[2 * t], 0.f),
                    fmaxf(acc[mf][t][3] + q_[2 * t + 1], 0.f));
                stash[lrA * 64 + (c2 ^ ((lrA & 7) * 4))] = *(unsigned*)&hA;
                stash[lrB * 64 + (c2 ^ ((lrB & 7) * 4))] = *(unsigned*)&hB;
            }
        }

        // ================= branch 0: h = agg @ W =================
        asm volatile("cp.async.wait_group 0;");
        __syncthreads();                       // agg stage visible
#pragma unroll
        for (int mf = 0; mf < 4; mf++)
#pragma unroll
            for (int t = 0; t < 4; t++)
#pragma unroll
                for (int r = 0; r < 4; r++) acc[mf][t][r] = 0.f;
        MMA_STAGE(0)
        __syncthreads();                       // all agg reads done
        if (s + 1 < nT) {                      // next x load overlaps epi below
            stage_load(asb, x4, (blockIdx.x + (s + 1) * gridDim.x) * BM, N, tid);
        }
        asm volatile("cp.async.commit_group;");

        // epi: y = relu(h*cd + b) + stash, write y, BN sums
#pragma unroll
        for (int mf = 0; mf < 4; mf++) {
            int lrA = mw * 64 + mf * 16 + gid;
            int lrB = lrA + 8;
            int rA = row0 + lrA, rB = rA + 8;
            float cdA = (rA < N) ? __ldg(&g_cdst[rA]) : 0.f;
            float cdB = (rB < N) ? __ldg(&g_cdst[rB]) : 0.f;
#pragma unroll
            for (int t = 0; t < 4; t++) {
                int col = nw * 32 + t * 8 + 2 * tig;
                int c2 = col2b + t * 4;
                unsigned sA = stash[lrA * 64 + (c2 ^ ((lrA & 7) * 4))];
                unsigned sB = stash[lrB * 64 + (c2 ^ ((lrB & 7) * 4))];
                float2 rsA = __half22float2(*(__half2*)&sA);
                float2 rsB = __half22float2(*(__half2*)&sB);
                if (rA < N) {
                    float v0 = fmaxf(acc[mf][t][0] * cdA + b_[2 * t], 0.f) + rsA.x;
                    float v1 = fmaxf(acc[mf][t][1] * cdA + b_[2 * t + 1], 0.f) + rsA.y;
                    *(float2*)&g_y[(size_t)rA * D + col] = make_float2(v0, v1);
                    ts[2 * t] += v0; tq[2 * t] += v0 * v0;
                    ts[2 * t + 1] += v1; tq[2 * t + 1] += v1 * v1;
                }
                if (rB < N) {
                    float v2 = fmaxf(acc[mf][t][2] * cdB + b_[2 * t], 0.f) + rsB.x;
                    float v3 = fmaxf(acc[mf][t][3] * cdB + b_[2 * t + 1], 0.f) + rsB.y;
                    *(float2*)&g_y[(size_t)rB * D + col] = make_float2(v2, v3);
                    ts[2 * t] += v2; tq[2 * t] += v2 * v2;
                    ts[2 * t + 1] += v3; tq[2 * t + 1] += v3 * v3;
                }
            }
        }
        __syncthreads();   // stash reads done before next tile's stash writes
    }

    // ---- BN sums: lanes gid 0..7 hold identical column sets -> reduce ----
#pragma unroll
    for (int i = 0; i < 8; i++) {
#pragma unroll
        for (int m = 4; m <= 16; m <<= 1) {
            ts[i] += __shfl_xor_sync(0xffffffffu, ts[i], m);
            tq[i] += __shfl_xor_sync(0xffffffffu, tq[i], m);
        }
    }
    if (gid == 0) {
#pragma unroll
        for (int i = 0; i < 8; i++) {
            int col = nw * 32 + (i >> 1) * 8 + 2 * tig + (i & 1);
            atomicAdd(&g_colsum[col], ts[i]);
            atomicAdd(&g_colsq[col], tq[i]);
        }
    }
}

// ---------------- BN parameter fold + apply ----------------------------------
__global__ void k_bnparams(const float* __restrict__ gamma, const float* __restrict__ beta, float invN) {
    int j = threadIdx.x;
    float mean = g_colsum[j] * invN;
    float var = fmaxf(g_colsq[j] * invN - mean * mean, 0.f);
    float s = rsqrtf(var + BN_EPS) * __ldg(&gamma[j]);
    g_scale[j] = s;
    g_shift[j] = __ldg(&beta[j]) - mean * s;
}

__global__ __launch_bounds__(256) void k_bnapply(float4* __restrict__ out4, int total4) {
    int i = blockIdx.x * blockDim.x + threadIdx.x;
    if (i >= total4) return;
    const float4* y4 = (const float4*)g_y;
    const float4* s4 = (const float4*)g_scale;
    const float4* t4 = (const float4*)g_shift;
    int c = i & 31;
    float4 v = y4[i];
    float4 s = s4[c];
    float4 t = t4[c];
    out4[i] = make_float4(v.x * s.x + t.x, v.y * s.y + t.y,
                          v.z * s.z + t.z, v.w * s.w + t.w);
}

// ---------------- launch ------------------------------------------------------
extern "C" void kernel_launch(void* const* d_in, const int* in_sizes, int n_in,
                              void* d_out, int out_size) {
    const float* x     = (const float*)d_in[0];
    const float* W     = (const float*)d_in[1];
    const float* b     = (const float*)d_in[2];
    const float* Wr    = (const float*)d_in[3];
    const float* br    = (const float*)d_in[4];
    const float* gamma = (const float*)d_in[5];
    const float* beta  = (const float*)d_in[6];
    const int*   src   = (const int*)d_in[7];
    const int*   dst   = (const int*)d_in[8];

    const int N = in_sizes[0] / D;
    const int E = in_sizes[7];

    void *p_agg, *p_odeg, *p_ideg;
    cudaGetSymbolAddress(&p_agg, g_agg);
    cudaGetSymbolAddress(&p_odeg, g_odeg);
    cudaGetSymbolAddress(&p_ideg, g_ideg);

    cudaMemsetAsync(p_agg, 0, (size_t)N * D * sizeof(float));
    cudaMemsetAsync(p_odeg, 0, (size_t)N * sizeof(int));
    cudaMemsetAsync(p_ideg, 0, (size_t)N * sizeof(int));

    k_degrees<<<(E + 255) / 256, 256>>>(src, dst, E);
    k_cnorm<<<(N + 255) / 256, 256>>>(N);

    {
        // 8 edges per warp -> 64 edges per 256-thread block
        int blocks = (E + 63) / 64;
        k_aggregate<<<blocks, 256>>>((const float4*)x, src, dst, E);
    }

    {
        const int smemBytes = 57344 * (int)sizeof(unsigned);  // 224 KB
        cudaFuncSetAttribute(k_gemm_tf32, cudaFuncAttributeMaxDynamicSharedMemorySize, smemBytes);
        int numTiles = (N + BM - 1) / BM;
        int grid = numTiles < 152 ? numTiles : 152;
        k_gemm_tf32<<<grid, 256, smemBytes>>>(
            (const float4*)x, W, b, Wr, br, N, numTiles);
    }

    k_bnparams<<<1, D>>>(gamma, beta, 1.0f / (float)N);
    {
        int total4 = N * (D / 4);
        k_bnapply<<<(total4 + 255) / 256, 256>>>((float4*)d_out, total4);
    }
}

// round 13
// speedup vs baseline: 1.2628x; 1.2502x over previous
#include <cuda_runtime.h>
#include <cuda_fp16.h>
#include <cstdint>

#define D 128
#define MAXN 100000
#define BM 64
#define BN_EPS 1e-5f

// ---------------- scratch (device globals; no runtime allocation) -----------
__device__ __align__(16) float g_agg[(size_t)MAXN * D];
__device__ __align__(16) float g_y[(size_t)MAXN * D];
__device__ float g_csrc[MAXN];
__device__ float g_cdst[MAXN];
__device__ int   g_odeg[MAXN];
__device__ int   g_ideg[MAXN];
__device__ __align__(16) float g_colsum[D];
__device__ __align__(16) float g_colsq[D];
__device__ __align__(16) float g_scale[D];
__device__ __align__(16) float g_shift[D];

// ---------------- degree histograms -----------------------------------------
__global__ void k_degrees(const int* __restrict__ src, const int* __restrict__ dst, int E) {
    int e = blockIdx.x * blockDim.x + threadIdx.x;
    if (e < E) {
        atomicAdd(&g_odeg[src[e]], 1);
        atomicAdd(&g_ideg[dst[e]], 1);
    }
}

// also zeroes the BN accumulators (saves two memset launches)
__global__ void k_cnorm(int N) {
    int i = blockIdx.x * blockDim.x + threadIdx.x;
    if (i < D) { g_colsum[i] = 0.f; g_colsq[i] = 0.f; }
    if (i < N) {
        g_csrc[i] = rsqrtf(fmaxf((float)g_odeg[i], 1.0f));
        g_cdst[i] = rsqrtf(fmaxf((float)g_ideg[i], 1.0f));
    }
}

// ---------------- edge aggregation: 8 edges per warp (4 lanes/edge) ----------
__global__ __launch_bounds__(256) void k_aggregate(
    const float4* __restrict__ x4, const int* __restrict__ src,
    const int* __restrict__ dst, int E) {
    int t = blockIdx.x * blockDim.x + threadIdx.x;
    int e = (t >> 5) * 8 + ((t & 31) >> 2);
    if (e >= E) return;
    int c = t & 3;
    int s = __ldg(&src[e]);
    int d = __ldg(&dst[e]);
    float cs = __ldg(&g_csrc[s]);
    const float4* xb = x4 + (size_t)s * 32;
    float4 v0 = __ldg(xb + c),      v1 = __ldg(xb + c + 4);
    float4 v2 = __ldg(xb + c + 8),  v3 = __ldg(xb + c + 12);
    float4 v4 = __ldg(xb + c + 16), v5 = __ldg(xb + c + 20);
    float4 v6 = __ldg(xb + c + 24), v7 = __ldg(xb + c + 28);
    float* p = g_agg + (size_t)d * D;
#define RED4(vv, off)                                                          \
    asm volatile("red.global.add.v4.f32 [%0], {%1, %2, %3, %4};"               \
                 :: "l"(p + (off) * 4), "f"((vv).x * cs), "f"((vv).y * cs),    \
                    "f"((vv).z * cs), "f"((vv).w * cs) : "memory")
    RED4(v0, c);      RED4(v1, c + 4);  RED4(v2, c + 8);  RED4(v3, c + 12);
    RED4(v4, c + 16); RED4(v5, c + 20); RED4(v6, c + 24); RED4(v7, c + 28);
#undef RED4
}

// ---------------- fp16 tensor-core fused dual GEMM ---------------------------
#define MMA_F16(d, a, b0_, b1_) \
    asm volatile("mma.sync.aligned.m16n8k16.row.col.f32.f16.f16.f32 " \
        "{%0,%1,%2,%3},{%4,%5,%6,%7},{%8,%9},{%0,%1,%2,%3};" \
        : "+f"(d[0]), "+f"(d[1]), "+f"(d[2]), "+f"(d[3]) \
        : "r"(a[0]), "r"(a[1]), "r"(a[2]), "r"(a[3]), "r"(b0_), "r"(b1_))

__device__ __forceinline__ unsigned h2u(__half2 h) {
    return *reinterpret_cast<unsigned*>(&h);
}

// MMA over one branch for the current 64-row fp16 stage. Warp tile m32 x n32.
// A smem: 64 rows x 64 fp16x2 words, word w of row r at r*64 + (w ^ ((r&7)*4)).
#define MMA_STAGE(ACC, BR)                                                         \
    _Pragma("unroll")                                                              \
    for (int jp = 0; jp < 8; jp++) {                                               \
        unsigned a[2][4];                                                          \
        int w0 = jp * 8 + tig;                                                     \
        _Pragma("unroll")                                                          \
        for (int mf = 0; mf < 2; mf++) {                                           \
            int row = mw * 32 + mf * 16 + gid;                                     \
            a[mf][0] = asb[row * 64 + (w0 ^ (gid * 4))];                           \
            a[mf][1] = asb[(row + 8) * 64 + (w0 ^ (gid * 4))];                     \
            a[mf][2] = asb[row * 64 + ((w0 + 4) ^ (gid * 4))];                     \
            a[mf][3] = asb[(row + 8) * 64 + ((w0 + 4) ^ (gid * 4))];               \
        }                                                                          \
        _Pragma("unroll")                                                          \
        for (int t = 0; t < 4; t++) {                                              \
            uint2 bf = ws2[(((nw * 2 + (BR)) * 4 + t) << 8) + jp * 32 + lane];     \
            MMA_F16(ACC[0][t], a[0], bf.x, bf.y);                                  \
            MMA_F16(ACC[1][t], a[1], bf.x, bf.y);                                  \
        }                                                                          \
    }

// Block: 256 thr = 8 warps = 2(m) x 4(n); warp tile m32 x n32, both branches.
// smem: ws 64KB (fp16 W/Wr fragment-major) + 2 x 16KB fp16 A stages = 96KB.
__global__ __launch_bounds__(256, 1) void k_gemm_fp16(
    const float4* __restrict__ x4, const float* __restrict__ W,
    const float* __restrict__ bb, const float* __restrict__ Wr,
    const float* __restrict__ brr, int N, int numTiles)
{
    extern __shared__ unsigned smem_u[];
    unsigned* ws  = smem_u;           // 16384 words = 64KB
    unsigned* as0 = smem_u + 16384;   //  4096 words = 16KB (64 rows fp16)
    unsigned* as1 = smem_u + 20480;   //  4096 words = 16KB
    const uint2* ws2 = (const uint2*)ws;

    const int tid  = threadIdx.x;
    const int lane = tid & 31;
    const int wid  = tid >> 5;
    const int mw   = wid >> 2;     // 0..1 (m group of 32 rows)
    const int nw   = wid & 3;      // 0..3 (n group of 32 cols)
    const int tig  = lane & 3;
    const int gid  = lane >> 2;

    const float4* agg4 = (const float4*)g_agg;

    // ---- one-time: fragment-major packed W/Wr in fp16 (RNE, unbiased) ----
    // cell (uint2): lane | kstep<<5 | t<<8 | br<<10 | nw<<11
    for (int cell = tid; cell < 8192; cell += 256) {
        int l   = cell & 31;
        int ks  = (cell >> 5) & 7;
        int t   = (cell >> 8) & 3;
        int cbr = (cell >> 10) & 1;
        int cnw = (cell >> 11) & 3;
        const float* Wb = cbr ? Wr : W;
        int n = cnw * 32 + t * 8 + (l >> 2);
        int k = ks * 16 + (l & 3) * 2;
        uint2 v;
        v.x = h2u(__floats2half2_rn(__ldg(&Wb[(k    ) * D + n]),
                                    __ldg(&Wb[(k + 1) * D + n])));
        v.y = h2u(__floats2half2_rn(__ldg(&Wb[(k + 8) * D + n]),
                                    __ldg(&Wb[(k + 9) * D + n])));
        ((uint2*)ws)[cell] = v;
    }

    // biases for this thread's 8 output columns
    float b_[8], q_[8];
#pragma unroll
    for (int t = 0; t < 4; t++) {
        int col = nw * 32 + t * 8 + 2 * tig;
        b_[2 * t] = __ldg(&bb[col]);   b_[2 * t + 1] = __ldg(&bb[col + 1]);
        q_[2 * t] = __ldg(&brr[col]);  q_[2 * t + 1] = __ldg(&brr[col + 1]);
    }

    float ts[8], tq[8];
#pragma unroll
    for (int i = 0; i < 8; i++) { ts[i] = 0.f; tq[i] = 0.f; }

    const int nT = (numTiles > blockIdx.x)
                 ? (numTiles - blockIdx.x + gridDim.x - 1) / gridDim.x : 0;
    const int totalS = nT * 2;

    // prologue: prefetch stage 0 (agg of tile 0) into registers
    float4 pf[8];
    {
        int row0 = blockIdx.x * BM;
#pragma unroll
        for (int i = 0; i < 8; i++) {
            int idx = tid + i * 256;
            int row = idx >> 5, kq = idx & 31;
            int grow = row0 + row;
            pf[i] = (grow < N) ? __ldg(&agg4[(size_t)grow * 32 + kq])
                               : make_float4(0.f, 0.f, 0.f, 0.f);
        }
    }

    float acc0[2][4][4], acc1[2][4][4];

    for (int s = 0; s < totalS; s++) {
        const int br   = s & 1;
        const int tile = blockIdx.x + (s >> 1) * gridDim.x;
        const int row0 = tile * BM;
        unsigned* buf = (s & 1) ? as1 : as0;

        // store prefetched fp32 tile as fp16 into swizzled smem
#pragma unroll
        for (int i = 0; i < 8; i++) {
            int idx = tid + i * 256;
            int row = idx >> 5, kq = idx & 31;
            uint2 u;
            u.x = h2u(__floats2half2_rn(pf[i].x, pf[i].y));
            u.y = h2u(__floats2half2_rn(pf[i].z, pf[i].w));
            *(uint2*)(buf + row * 64 + ((2 * kq) ^ ((row & 7) * 4))) = u;
        }
        __syncthreads();   // stage visible; prior readers of this buf all done

        // prefetch stage s+1 (hidden under this stage's MMAs)
        if (s + 1 < totalS) {
            const float4* nsrc = ((s + 1) & 1) ? x4 : agg4;
            int nrow0 = (blockIdx.x + ((s + 1) >> 1) * gridDim.x) * BM;
#pragma unroll
            for (int i = 0; i < 8; i++) {
                int idx = tid + i * 256;
                int row = idx >> 5, kq = idx & 31;
                int grow = nrow0 + row;
                pf[i] = (grow < N) ? __ldg(&nsrc[(size_t)grow * 32 + kq])
                                   : make_float4(0.f, 0.f, 0.f, 0.f);
            }
        }

        const unsigned* asb = buf;
        if (br == 0) {
#pragma unroll
            for (int mf = 0; mf < 2; mf++)
#pragma unroll
                for (int t = 0; t < 4; t++)
#pragma unroll
                    for (int r = 0; r < 4; r++) { acc0[mf][t][r] = 0.f; acc1[mf][t][r] = 0.f; }
            MMA_STAGE(acc0, 0)
        } else {
            MMA_STAGE(acc1, 1)

            // epilogue: y = relu(h*cd + b) + relu(res + q), write y, BN sums
#pragma unroll
            for (int mf = 0; mf < 2; mf++) {
                int rA = row0 + mw * 32 + mf * 16 + gid;
                int rB = rA + 8;
                float cdA = (rA < N) ? __ldg(&g_cdst[rA]) : 0.f;
                float cdB = (rB < N) ? __ldg(&g_cdst[rB]) : 0.f;
#pragma unroll
                for (int t = 0; t < 4; t++) {
                    int col = nw * 32 + t * 8 + 2 * tig;
                    if (rA < N) {
                        float v0 = fmaxf(acc0[mf][t][0] * cdA + b_[2 * t], 0.f)
                                 + fmaxf(acc1[mf][t][0] + q_[2 * t], 0.f);
                        float v1 = fmaxf(acc0[mf][t][1] * cdA + b_[2 * t + 1], 0.f)
                                 + fmaxf(acc1[mf][t][1] + q_[2 * t + 1], 0.f);
                        *(float2*)&g_y[(size_t)rA * D + col] = make_float2(v0, v1);
                        ts[2 * t] += v0; tq[2 * t] += v0 * v0;
                        ts[2 * t + 1] += v1; tq[2 * t + 1] += v1 * v1;
                    }
                    if (rB < N) {
                        float v2 = fmaxf(acc0[mf][t][2] * cdB + b_[2 * t], 0.f)
                                 + fmaxf(acc1[mf][t][2] + q_[2 * t], 0.f);
                        float v3 = fmaxf(acc0[mf][t][3] * cdB + b_[2 * t + 1], 0.f)
                                 + fmaxf(acc1[mf][t][3] + q_[2 * t + 1], 0.f);
                        *(float2*)&g_y[(size_t)rB * D + col] = make_float2(v2, v3);
                        ts[2 * t] += v2; tq[2 * t] += v2 * v2;
                        ts[2 * t + 1] += v3; tq[2 * t + 1] += v3 * v3;
                    }
                }
            }
        }
    }

    // ---- BN sums: lanes gid 0..7 hold identical column sets -> reduce ----
#pragma unroll
    for (int i = 0; i < 8; i++) {
#pragma unroll
        for (int m = 4; m <= 16; m <<= 1) {
            ts[i] += __shfl_xor_sync(0xffffffffu, ts[i], m);
            tq[i] += __shfl_xor_sync(0xffffffffu, tq[i], m);
        }
    }
    if (gid == 0) {
#pragma unroll
        for (int i = 0; i < 8; i++) {
            int col = nw * 32 + (i >> 1) * 8 + 2 * tig + (i & 1);
            atomicAdd(&g_colsum[col], ts[i]);
            atomicAdd(&g_colsq[col], tq[i]);
        }
    }
}

// ---------------- BN parameter fold + apply ----------------------------------
__global__ void k_bnparams(const float* __restrict__ gamma, const float* __restrict__ beta, float invN) {
    int j = threadIdx.x;
    float mean = g_colsum[j] * invN;
    float var = fmaxf(g_colsq[j] * invN - mean * mean, 0.f);
    float s = rsqrtf(var + BN_EPS) * __ldg(&gamma[j]);
    g_scale[j] = s;
    g_shift[j] = __ldg(&beta[j]) - mean * s;
}

__global__ __launch_bounds__(256) void k_bnapply(float4* __restrict__ out4, int total4) {
    int i = blockIdx.x * blockDim.x + threadIdx.x;
    if (i >= total4) return;
    const float4* y4 = (const float4*)g_y;
    const float4* s4 = (const float4*)g_scale;
    const float4* t4 = (const float4*)g_shift;
    int c = i & 31;
    float4 v = y4[i];
    float4 s = s4[c];
    float4 t = t4[c];
    out4[i] = make_float4(v.x * s.x + t.x, v.y * s.y + t.y,
                          v.z * s.z + t.z, v.w * s.w + t.w);
}

// ---------------- launch ------------------------------------------------------
extern "C" void kernel_launch(void* const* d_in, const int* in_sizes, int n_in,
                              void* d_out, int out_size) {
    const float* x     = (const float*)d_in[0];
    const float* W     = (const float*)d_in[1];
    const float* b     = (const float*)d_in[2];
    const float* Wr    = (const float*)d_in[3];
    const float* br    = (const float*)d_in[4];
    const float* gamma = (const float*)d_in[5];
    const float* beta  = (const float*)d_in[6];
    const int*   src   = (const int*)d_in[7];
    const int*   dst   = (const int*)d_in[8];

    const int N = in_sizes[0] / D;
    const int E = in_sizes[7];

    void *p_agg, *p_odeg, *p_ideg;
    cudaGetSymbolAddress(&p_agg, g_agg);
    cudaGetSymbolAddress(&p_odeg, g_odeg);
    cudaGetSymbolAddress(&p_ideg, g_ideg);

    cudaMemsetAsync(p_agg, 0, (size_t)N * D * sizeof(float));
    cudaMemsetAsync(p_odeg, 0, (size_t)N * sizeof(int));
    cudaMemsetAsync(p_ideg, 0, (size_t)N * sizeof(int));

    k_degrees<<<(E + 255) / 256, 256>>>(src, dst, E);
    k_cnorm<<<(N + 255) / 256, 256>>>(N);

    {
        // 8 edges per warp -> 64 edges per 256-thread block
        int blocks = (E + 63) / 64;
        k_aggregate<<<blocks, 256>>>((const float4*)x, src, dst, E);
    }

    {
        const int smemBytes = 24576 * (int)sizeof(unsigned);  // 96 KB
        cudaFuncSetAttribute(k_gemm_fp16, cudaFuncAttributeMaxDynamicSharedMemorySize, smemBytes);
        int numTiles = (N + BM - 1) / BM;
        int grid = numTiles < 152 ? numTiles : 152;
        k_gemm_fp16<<<grid, 256, smemBytes>>>(
            (const float4*)x, W, b, Wr, br, N, numTiles);
    }

    k_bnparams<<<1, D>>>(gamma, beta, 1.0f / (float)N);
    {
        int total4 = N * (D / 4);
        k_bnapply<<<(total4 + 255) / 256, 256>>>((float4*)d_out, total4);
    }
}

// round 14
// speedup vs baseline: 1.4727x; 1.1662x over previous
#include <cuda_runtime.h>
#include <cuda_fp16.h>
#include <cstdint>

#define D 128
#define MAXN 100000
#define BM 64
#define BN_EPS 1e-5f

// ---------------- scratch (device globals; no runtime allocation) -----------
__device__ __align__(16) __half g_aggh[(size_t)MAXN * D];  // fp16 aggregated msgs
__device__ __align__(16) __half g_xh[(size_t)MAXN * D];    // fp16 copy of x
__device__ __align__(16) float g_y[(size_t)MAXN * D];
__device__ float g_csrc[MAXN];
__device__ float g_cdst[MAXN];
__device__ int   g_odeg[MAXN];
__device__ int   g_ideg[MAXN];
__device__ __align__(16) float g_colsum[D];
__device__ __align__(16) float g_colsq[D];
__device__ __align__(16) float g_scale[D];
__device__ __align__(16) float g_shift[D];

__device__ __forceinline__ unsigned h2u(__half2 h) {
    return *reinterpret_cast<unsigned*>(&h);
}

// ---------------- prep: degree histograms + x -> fp16 cast (one launch) ------
__global__ void k_prep(const int* __restrict__ src, const int* __restrict__ dst, int E,
                       const float4* __restrict__ x4, int xChunks, int xBlocks) {
    if ((int)blockIdx.x < xBlocks) {
        int i = blockIdx.x * 256 + threadIdx.x;          // uint4 chunk (8 halves)
        if (i < xChunks) {
            float4 aL = __ldg(&x4[2 * i]);
            float4 aH = __ldg(&x4[2 * i + 1]);
            uint4 o;
            o.x = h2u(__floats2half2_rn(aL.x, aL.y));
            o.y = h2u(__floats2half2_rn(aL.z, aL.w));
            o.z = h2u(__floats2half2_rn(aH.x, aH.y));
            o.w = h2u(__floats2half2_rn(aH.z, aH.w));
            ((uint4*)g_xh)[i] = o;
        }
    } else {
        int e = ((int)blockIdx.x - xBlocks) * 256 + threadIdx.x;
        if (e < E) {
            atomicAdd(&g_odeg[src[e]], 1);
            atomicAdd(&g_ideg[dst[e]], 1);
        }
    }
}

// also zeroes the BN accumulators (saves two memset launches)
__global__ void k_cnorm(int N) {
    int i = blockIdx.x * blockDim.x + threadIdx.x;
    if (i < D) { g_colsum[i] = 0.f; g_colsq[i] = 0.f; }
    if (i < N) {
        g_csrc[i] = rsqrtf(fmaxf((float)g_odeg[i], 1.0f));
        g_cdst[i] = rsqrtf(fmaxf((float)g_ideg[i], 1.0f));
    }
}

// ---------------- edge aggregation: fp16 gather + fp16x2 vector reductions ---
// 8 edges per warp, 4 lanes/edge; lane handles 16B chunks c, c+4, c+8, c+12
__global__ __launch_bounds__(256) void k_aggregate(
    const int* __restrict__ src, const int* __restrict__ dst, int E) {
    int t = blockIdx.x * blockDim.x + threadIdx.x;
    int e = (t >> 5) * 8 + ((t & 31) >> 2);
    if (e >= E) return;
    int c = t & 3;
    int s = __ldg(&src[e]);
    int d = __ldg(&dst[e]);
    float cs = __ldg(&g_csrc[s]);
    const uint4* xb = (const uint4*)(g_xh + (size_t)s * D);
    uint4 u[4];
    u[0] = __ldg(xb + c);     u[1] = __ldg(xb + c + 4);
    u[2] = __ldg(xb + c + 8); u[3] = __ldg(xb + c + 12);
    __half* p = g_aggh + (size_t)d * D;
#pragma unroll
    for (int i = 0; i < 4; i++) {
        int ch = c + i * 4;
        unsigned w[4];
#pragma unroll
        for (int j = 0; j < 4; j++) {
            float2 f = __half22float2(*(__half2*)&((unsigned*)&u[i])[j]);
            w[j] = h2u(__floats2half2_rn(f.x * cs, f.y * cs));
        }
        asm volatile("red.global.add.noftz.v4.f16x2 [%0], {%1, %2, %3, %4};"
                     :: "l"(p + ch * 8), "r"(w[0]), "r"(w[1]), "r"(w[2]), "r"(w[3])
                     : "memory");
    }
}

// ---------------- fp16 tensor-core fused dual GEMM ---------------------------
#define MMA_F16(d, a, b0_, b1_) \
    asm volatile("mma.sync.aligned.m16n8k16.row.col.f32.f16.f16.f32 " \
        "{%0,%1,%2,%3},{%4,%5,%6,%7},{%8,%9},{%0,%1,%2,%3};" \
        : "+f"(d[0]), "+f"(d[1]), "+f"(d[2]), "+f"(d[3]) \
        : "r"(a[0]), "r"(a[1]), "r"(a[2]), "r"(a[3]), "r"(b0_), "r"(b1_))

// one 64-row fp16 tile stage via cp.async (16B chunks, swizzled)
__device__ __forceinline__ void stage_load(unsigned* buf, const __half* __restrict__ srcb,
                                           int row0, int N, int tid) {
#pragma unroll
    for (int i = 0; i < 4; i++) {
        int idx = tid + i * 256;
        int row = idx >> 4, kq = idx & 15;
        int grow = row0 + row;
        unsigned daddr = (unsigned)__cvta_generic_to_shared(
            buf + row * 64 + ((kq * 4) ^ ((row & 7) * 4)));
        const uint4* s = (const uint4*)(srcb + (size_t)(grow < N ? grow : 0) * D) + kq;
        int sz = grow < N ? 16 : 0;
        asm volatile("cp.async.cg.shared.global [%0], [%1], 16, %2;"
                     :: "r"(daddr), "l"(s), "r"(sz));
    }
}

// MMA over one branch for the current 64-row fp16 stage. Warp tile m32 x n32.
#define MMA_STAGE(ACC, BR)                                                         \
    _Pragma("unroll")                                                              \
    for (int jp = 0; jp < 8; jp++) {                                               \
        unsigned a[2][4];                                                          \
        int w0 = jp * 8 + tig;                                                     \
        _Pragma("unroll")                                                          \
        for (int mf = 0; mf < 2; mf++) {                                           \
            int row = mw * 32 + mf * 16 + gid;                                     \
            a[mf][0] = asb[row * 64 + (w0 ^ (gid * 4))];                           \
            a[mf][1] = asb[(row + 8) * 64 + (w0 ^ (gid * 4))];                     \
            a[mf][2] = asb[row * 64 + ((w0 + 4) ^ (gid * 4))];                     \
            a[mf][3] = asb[(row + 8) * 64 + ((w0 + 4) ^ (gid * 4))];               \
        }                                                                          \
        _Pragma("unroll")                                                          \
        for (int t = 0; t < 4; t++) {                                              \
            uint2 bf = ws2[(((nw * 2 + (BR)) * 4 + t) << 8) + jp * 32 + lane];     \
            MMA_F16(ACC[0][t], a[0], bf.x, bf.y);                                  \
            MMA_F16(ACC[1][t], a[1], bf.x, bf.y);                                  \
        }                                                                          \
    }

// Block: 256 thr = 8 warps = 2(m) x 4(n); warp tile m32 x n32, both branches.
// smem: ws 64KB (fp16 W/Wr fragment-major) + 2 x 16KB fp16 A stages = 96KB.
__global__ __launch_bounds__(256, 1) void k_gemm_fp16(
    const float* __restrict__ W, const float* __restrict__ bb,
    const float* __restrict__ Wr, const float* __restrict__ brr,
    int N, int numTiles)
{
    extern __shared__ unsigned smem_u[];
    unsigned* ws  = smem_u;           // 16384 words = 64KB
    unsigned* as0 = smem_u + 16384;   //  4096 words = 16KB (64 rows fp16)
    unsigned* as1 = smem_u + 20480;   //  4096 words = 16KB
    const uint2* ws2 = (const uint2*)ws;

    const int tid  = threadIdx.x;
    const int lane = tid & 31;
    const int wid  = tid >> 5;
    const int mw   = wid >> 2;     // 0..1 (m group of 32 rows)
    const int nw   = wid & 3;      // 0..3 (n group of 32 cols)
    const int tig  = lane & 3;
    const int gid  = lane >> 2;

    // ---- one-time: fragment-major packed W/Wr in fp16 (RNE, unbiased) ----
    for (int cell = tid; cell < 8192; cell += 256) {
        int l   = cell & 31;
        int ks  = (cell >> 5) & 7;
        int t   = (cell >> 8) & 3;
        int cbr = (cell >> 10) & 1;
        int cnw = (cell >> 11) & 3;
        const float* Wb = cbr ? Wr : W;
        int n = cnw * 32 + t * 8 + (l >> 2);
        int k = ks * 16 + (l & 3) * 2;
        uint2 v;
        v.x = h2u(__floats2half2_rn(__ldg(&Wb[(k    ) * D + n]),
                                    __ldg(&Wb[(k + 1) * D + n])));
        v.y = h2u(__floats2half2_rn(__ldg(&Wb[(k + 8) * D + n]),
                                    __ldg(&Wb[(k + 9) * D + n])));
        ((uint2*)ws)[cell] = v;
    }

    // biases for this thread's 8 output columns
    float b_[8], q_[8];
#pragma unroll
    for (int t = 0; t < 4; t++) {
        int col = nw * 32 + t * 8 + 2 * tig;
        b_[2 * t] = __ldg(&bb[col]);   b_[2 * t + 1] = __ldg(&bb[col + 1]);
        q_[2 * t] = __ldg(&brr[col]);  q_[2 * t + 1] = __ldg(&brr[col + 1]);
    }

    float ts[8], tq[8];
#pragma unroll
    for (int i = 0; i < 8; i++) { ts[i] = 0.f; tq[i] = 0.f; }

    const int nT = (numTiles > (int)blockIdx.x)
                 ? (numTiles - blockIdx.x + gridDim.x - 1) / gridDim.x : 0;
    const int totalS = nT * 2;

    // prologue: stages 0 (agg of tile0) and 1 (xh of tile0)
    stage_load(as0, g_aggh, blockIdx.x * BM, N, tid);
    asm volatile("cp.async.commit_group;");
    stage_load(as1, g_xh, blockIdx.x * BM, N, tid);
    asm volatile("cp.async.commit_group;");

    float acc0[2][4][4], acc1[2][4][4];

    for (int s = 0; s < totalS; s++) {
        const int br   = s & 1;
        const int tile = blockIdx.x + (s >> 1) * gridDim.x;
        const int row0 = tile * BM;

        asm volatile("cp.async.wait_group 1;");
        __syncthreads();
        const unsigned* asb = br ? as1 : as0;

        if (br == 0) {
#pragma unroll
            for (int mf = 0; mf < 2; mf++)
#pragma unroll
                for (int t = 0; t < 4; t++)
#pragma unroll
                    for (int r = 0; r < 4; r++) { acc0[mf][t][r] = 0.f; acc1[mf][t][r] = 0.f; }
            MMA_STAGE(acc0, 0)
        } else {
            MMA_STAGE(acc1, 1)
        }

        __syncthreads();  // all reads of asb done before overwrite

        int s2 = s + 2;
        if (s2 < totalS) {
            int t2 = blockIdx.x + (s2 >> 1) * gridDim.x;
            stage_load((s2 & 1) ? as1 : as0, (s2 & 1) ? g_xh : g_aggh, t2 * BM, N, tid);
        }
        asm volatile("cp.async.commit_group;");

        if (br == 1) {
            // epilogue: y = relu(h*cd + b) + relu(res + q), write y, BN sums
#pragma unroll
            for (int mf = 0; mf < 2; mf++) {
                int rA = row0 + mw * 32 + mf * 16 + gid;
                int rB = rA + 8;
                float cdA = (rA < N) ? __ldg(&g_cdst[rA]) : 0.f;
                float cdB = (rB < N) ? __ldg(&g_cdst[rB]) : 0.f;
#pragma unroll
                for (int t = 0; t < 4; t++) {
                    int col = nw * 32 + t * 8 + 2 * tig;
                    if (rA < N) {
                        float v0 = fmaxf(acc0[mf][t][0] * cdA + b_[2 * t], 0.f)
                                 + fmaxf(acc1[mf][t][0] + q_[2 * t], 0.f);
                        float v1 = fmaxf(acc0[mf][t][1] * cdA + b_[2 * t + 1], 0.f)
                                 + fmaxf(acc1[mf][t][1] + q_[2 * t + 1], 0.f);
                        *(float2*)&g_y[(size_t)rA * D + col] = make_float2(v0, v1);
                        ts[2 * t] += v0; tq[2 * t] += v0 * v0;
                        ts[2 * t + 1] += v1; tq[2 * t + 1] += v1 * v1;
                    }
                    if (rB < N) {
                        float v2 = fmaxf(acc0[mf][t][2] * cdB + b_[2 * t], 0.f)
                                 + fmaxf(acc1[mf][t][2] + q_[2 * t], 0.f);
                        float v3 = fmaxf(acc0[mf][t][3] * cdB + b_[2 * t + 1], 0.f)
                                 + fmaxf(acc1[mf][t][3] + q_[2 * t + 1], 0.f);
                        *(float2*)&g_y[(size_t)rB * D + col] = make_float2(v2, v3);
                        ts[2 * t] += v2; tq[2 * t] += v2 * v2;
                        ts[2 * t + 1] += v3; tq[2 * t + 1] += v3 * v3;
                    }
                }
            }
        }
    }

    // ---- BN sums: lanes gid 0..7 hold identical column sets -> reduce ----
#pragma unroll
    for (int i = 0; i < 8; i++) {
#pragma unroll
        for (int m = 4; m <= 16; m <<= 1) {
            ts[i] += __shfl_xor_sync(0xffffffffu, ts[i], m);
            tq[i] += __shfl_xor_sync(0xffffffffu, tq[i], m);
        }
    }
    if (gid == 0) {
#pragma unroll
        for (int i = 0; i < 8; i++) {
            int col = nw * 32 + (i >> 1) * 8 + 2 * tig + (i & 1);
            atomicAdd(&g_colsum[col], ts[i]);
            atomicAdd(&g_colsq[col], tq[i]);
        }
    }
}

// ---------------- BN parameter fold + apply ----------------------------------
__global__ void k_bnparams(const float* __restrict__ gamma, const float* __restrict__ beta, float invN) {
    int j = threadIdx.x;
    float mean = g_colsum[j] * invN;
    float var = fmaxf(g_colsq[j] * invN - mean * mean, 0.f);
    float s = rsqrtf(var + BN_EPS) * __ldg(&gamma[j]);
    g_scale[j] = s;
    g_shift[j] = __ldg(&beta[j]) - mean * s;
}

__global__ __launch_bounds__(256) void k_bnapply(float4* __restrict__ out4, int total4) {
    int i = blockIdx.x * blockDim.x + threadIdx.x;
    if (i >= total4) return;
    const float4* y4 = (const float4*)g_y;
    const float4* s4 = (const float4*)g_scale;
    const float4* t4 = (const float4*)g_shift;
    int c = i & 31;
    float4 v = y4[i];
    float4 s = s4[c];
    float4 t = t4[c];
    out4[i] = make_float4(v.x * s.x + t.x, v.y * s.y + t.y,
                          v.z * s.z + t.z, v.w * s.w + t.w);
}

// ---------------- launch ------------------------------------------------------
extern "C" void kernel_launch(void* const* d_in, const int* in_sizes, int n_in,
                              void* d_out, int out_size) {
    const float* x     = (const float*)d_in[0];
    const float* W     = (const float*)d_in[1];
    const float* b     = (const float*)d_in[2];
    const float* Wr    = (const float*)d_in[3];
    const float* br    = (const float*)d_in[4];
    const float* gamma = (const float*)d_in[5];
    const float* beta  = (const float*)d_in[6];
    const int*   src   = (const int*)d_in[7];
    const int*   dst   = (const int*)d_in[8];

    const int N = in_sizes[0] / D;
    const int E = in_sizes[7];

    void *p_aggh, *p_odeg, *p_ideg;
    cudaGetSymbolAddress(&p_aggh, g_aggh);
    cudaGetSymbolAddress(&p_odeg, g_odeg);
    cudaGetSymbolAddress(&p_ideg, g_ideg);

    cudaMemsetAsync(p_aggh, 0, (size_t)N * D * sizeof(__half));
    cudaMemsetAsync(p_odeg, 0, (size_t)N * sizeof(int));
    cudaMemsetAsync(p_ideg, 0, (size_t)N * sizeof(int));

    {
        int xChunks = N * (D / 8);                 // 16B chunks of xh
        int xBlocks = (xChunks + 255) / 256;
        int eBlocks = (E + 255) / 256;
        k_prep<<<xBlocks + eBlocks, 256>>>(src, dst, E, (const float4*)x, xChunks, xBlocks);
    }
    k_cnorm<<<(N + 255) / 256, 256>>>(N);

    {
        // 8 edges per warp -> 64 edges per 256-thread block
        int blocks = (E + 63) / 64;
        k_aggregate<<<blocks, 256>>>(src, dst, E);
    }

    {
        const int smemBytes = 24576 * (int)sizeof(unsigned);  // 96 KB
        cudaFuncSetAttribute(k_gemm_fp16, cudaFuncAttributeMaxDynamicSharedMemorySize, smemBytes);
        int numTiles = (N + BM - 1) / BM;
        int grid = numTiles < 152 ? numTiles : 152;
        k_gemm_fp16<<<grid, 256, smemBytes>>>(W, b, Wr, br, N, numTiles);
    }

    k_bnparams<<<1, D>>>(gamma, beta, 1.0f / (float)N);
    {
        int total4 = N * (D / 4);
        k_bnapply<<<(total4 + 255) / 256, 256>>>((float4*)d_out, total4);
    }
}